// round 7
// baseline (speedup 1.0000x reference)
#include <cuda_runtime.h>
#include <cstdint>

constexpr int B  = 4;
constexpr int C  = 512;
constexpr int T  = 3;
constexpr int HW = 2304;   // 48*48
constexpr int N3 = 6912;   // 3*HW
constexpr int G  = 4;
constexpr int CG = C / G;  // 128
constexpr float EPS = 1e-6f;

// Scratch
__device__ float g_hnt[(size_t)B * N3 * C];   // normalized, transposed [b][t*HW+p][c]
__device__ float g_qt [(size_t)B * HW * C];   // q transposed [b][p][c] (also skip)
__device__ float g_kt [(size_t)B * N3 * C];   // k transposed [b][m][c]
__device__ float g_v  [(size_t)B * C * N3];   // v [b][c][m]
__device__ float g_sc [(size_t)B * HW * N3];  // scores / attn [b][p][m]
__device__ float g_ot [(size_t)B * HW * C];   // attn out transposed [b][p][c]
__device__ float g_stats[2 * B * G];

__device__ __forceinline__ uint32_t smem_u32(const void* p) {
    return (uint32_t)__cvta_generic_to_shared(p);
}
#define CP_ASYNC16(sm, gm) \
    asm volatile("cp.async.ca.shared.global [%0], [%1], 16;" :: "r"(sm), "l"(gm))
#define CP_COMMIT asm volatile("cp.async.commit_group;")
#define CP_WAIT1  asm volatile("cp.async.wait_group 1;")
#define CP_WAIT0  asm volatile("cp.async.wait_group 0;")

__device__ __forceinline__ void ldm_x4(uint32_t* r, uint32_t addr) {
    asm volatile("ldmatrix.sync.aligned.m8n8.x4.shared.b16 {%0,%1,%2,%3}, [%4];"
        : "=r"(r[0]), "=r"(r[1]), "=r"(r[2]), "=r"(r[3]) : "r"(addr));
}
__device__ __forceinline__ void mma_tf32(float* c, const uint32_t* a, const uint32_t* b) {
    asm volatile("mma.sync.aligned.m16n8k8.row.col.f32.tf32.tf32.f32 "
        "{%0,%1,%2,%3}, {%4,%5,%6,%7}, {%8,%9}, {%0,%1,%2,%3};"
        : "+f"(c[0]), "+f"(c[1]), "+f"(c[2]), "+f"(c[3])
        : "r"(a[0]), "r"(a[1]), "r"(a[2]), "r"(a[3]), "r"(b[0]), "r"(b[1]));
}

// ---------------------------------------------------------------------------
// GroupNorm
// ---------------------------------------------------------------------------
__global__ void zero_stats_kernel() {
    if (threadIdx.x < 2 * B * G) g_stats[threadIdx.x] = 0.f;
}

__global__ void gn_stats_kernel(const float* __restrict__ x) {
    const int bg = blockIdx.x;
    const int b = bg >> 2, g = bg & 3;
    const int TOT4 = CG * T * HW / 4;
    const int PER  = TOT4 / 16;
    const int start = blockIdx.y * PER;

    float s = 0.f, ss = 0.f;
    for (int i = start + threadIdx.x; i < start + PER; i += blockDim.x) {
        int cl = i / (T * HW / 4);
        int r  = i - cl * (T * HW / 4);
        int t  = r / (HW / 4);
        int p4 = r - t * (HW / 4);
        float4 v = reinterpret_cast<const float4*>(x)[
            ((size_t)(t * B + b) * C + g * CG + cl) * (HW / 4) + p4];
        s  += v.x + v.y + v.z + v.w;
        ss += v.x * v.x + v.y * v.y + v.z * v.z + v.w * v.w;
    }
    __shared__ float rs[8], rss[8];
    #pragma unroll
    for (int o = 16; o; o >>= 1) {
        s  += __shfl_xor_sync(0xffffffffu, s, o);
        ss += __shfl_xor_sync(0xffffffffu, ss, o);
    }
    if ((threadIdx.x & 31) == 0) { rs[threadIdx.x >> 5] = s; rss[threadIdx.x >> 5] = ss; }
    __syncthreads();
    if (threadIdx.x == 0) {
        float a = 0.f, c = 0.f;
        #pragma unroll
        for (int i = 0; i < 8; i++) { a += rs[i]; c += rss[i]; }
        atomicAdd(&g_stats[2 * bg],     a);
        atomicAdd(&g_stats[2 * bg + 1], c);
    }
}

// normalize + affine + transpose -> g_hnt[b][t*HW+p][c]
__global__ void gn_apply_t_kernel(const float* __restrict__ x,
                                  const float* __restrict__ scale,
                                  const float* __restrict__ bias) {
    __shared__ float tile[32][33];
    const int bt = blockIdx.z;
    const int b = bt / T, t = bt - b * T;
    const int p0 = blockIdx.x << 5, c0 = blockIdx.y << 5;
    const int tx = threadIdx.x, ty = threadIdx.y;  // 32 x 8
    const float nrm = 1.f / (float)(CG * T * HW);

    #pragma unroll
    for (int kk = 0; kk < 4; kk++) {
        int c = c0 + ty + kk * 8;
        int g = c >> 7;
        float sum = g_stats[2 * (b * G + g)];
        float sq  = g_stats[2 * (b * G + g) + 1];
        float mean = sum * nrm;
        float var  = sq * nrm - mean * mean;
        float rstd = rsqrtf(var + EPS);
        float a = rstd * scale[c];
        float d = bias[c] - mean * a;
        float v = x[((size_t)(t * B + b) * C + c) * HW + p0 + tx];
        tile[ty + kk * 8][tx] = v * a + d;
    }
    __syncthreads();
    #pragma unroll
    for (int kk = 0; kk < 4; kk++) {
        int p = p0 + ty + kk * 8;
        g_hnt[(size_t)b * N3 * C + (size_t)(t * HW + p) * C + c0 + tx] = tile[tx][ty + kk * 8];
    }
}

// ---------------------------------------------------------------------------
// TF32 mma.sync GEMM: 128x256 CTA tile, BK=32, 8 warps (2x4), warp 64x64.
// 3-stage cp.async ring, ldmatrix fragments, quad-XOR swizzle.
// Cm[m,n] = alpha * sum_k A[m,k]*Bm[n,k] (+bias) (+skip^T)
// A:[M][K] K-major, Bm:[N][K] K-major.
// BIAS_MODE: 0 none, 1 bias[row m], 2 bias[col n]. skip read [n][m].
// ---------------------------------------------------------------------------
constexpr int TILE_A_F = 128 * 32;                  // floats, A stage
constexpr int TILE_B_F = 256 * 32;                  // floats, B stage
constexpr int STAGE_F  = TILE_A_F + TILE_B_F;       // 12288 floats = 48KB
constexpr int GEMM_SMEM = 3 * STAGE_F * 4;          // 147456 bytes

template <int BIAS_MODE, bool HAS_SKIP>
__global__ __launch_bounds__(256)
void mma_gemm(const float* __restrict__ A, int lda, long long sA,
              const float* __restrict__ Bm, int ldb, long long sB,
              float* __restrict__ Cm, int ldc, long long sC,
              int K, float alpha, const float* __restrict__ bias,
              const float* __restrict__ skip, int ldsk, long long sSk) {
    extern __shared__ __align__(16) float dyn[];

    const int bz = blockIdx.z;
    A  += (size_t)bz * sA;
    Bm += (size_t)bz * sB;
    Cm += (size_t)bz * sC;
    if (HAS_SKIP) skip += (size_t)bz * sSk;

    const int bm = blockIdx.x * 128, bn = blockIdx.y * 256;
    const int tid = threadIdx.x, wid = tid >> 5, lane = tid & 31;
    const int wm = wid & 1, wn = wid >> 1;      // warp grid 2 (M) x 4 (N)
    const int gr = lane >> 2, t4 = lane & 3;
    const int grp = lane >> 3, rowin = lane & 7;
    const int qhiA = grp >> 1;
    const int qhiB = grp & 1;

    // gmem -> smem staging: thread -> row r = tid>>1, 4 16B chunks at q0..q0+3
    const int r  = tid >> 1;
    const int q0 = (tid & 1) * 4;
    const float* Arow  = A  + (size_t)(bm + r) * lda;
    const float* Brow0 = Bm + (size_t)(bn + r) * ldb;
    const float* Brow1 = Bm + (size_t)(bn + 128 + r) * ldb;
    uint32_t off[4];
    #pragma unroll
    for (int j = 0; j < 4; j++)
        off[j] = (r * 32 + (((q0 + j) ^ (r & 7)) << 2)) * 4;  // bytes within sub-tile
    uint32_t aBase[3], bBase[3];
    #pragma unroll
    for (int s = 0; s < 3; s++) {
        aBase[s] = smem_u32(dyn + s * STAGE_F);
        bBase[s] = aBase[s] + TILE_A_F * 4;
    }
    auto stage = [&](int k0, int s) {
        #pragma unroll
        for (int j = 0; j < 4; j++)
            CP_ASYNC16(aBase[s] + off[j], Arow + k0 + (q0 + j) * 4);
        #pragma unroll
        for (int j = 0; j < 4; j++)
            CP_ASYNC16(bBase[s] + off[j], Brow0 + k0 + (q0 + j) * 4);
        #pragma unroll
        for (int j = 0; j < 4; j++)
            CP_ASYNC16(bBase[s] + 16384 + off[j], Brow1 + k0 + (q0 + j) * 4);
        CP_COMMIT;
    };

    // fragment row byte-offsets (within the operand sub-tile)
    uint32_t aRow[4], bRow[4];
    #pragma unroll
    for (int mf = 0; mf < 4; mf++)
        aRow[mf] = (uint32_t)(wm * 64 + mf * 16 + (grp & 1) * 8 + rowin) * 128;
    #pragma unroll
    for (int p = 0; p < 4; p++)
        bRow[p] = (uint32_t)(wn * 64 + p * 16 + (grp >> 1) * 8 + rowin) * 128;

    float acc[4][8][4];
    #pragma unroll
    for (int i = 0; i < 4; i++)
        #pragma unroll
        for (int j = 0; j < 8; j++)
            #pragma unroll
            for (int q = 0; q < 4; q++) acc[i][j][q] = 0.f;

    const int nk = K >> 5;
    stage(0, 0);
    stage(32, 1);

    int s_cur = 0, s_nxt = 2;
    for (int kt = 0; kt < nk; kt++) {
        if (kt == nk - 1) { CP_WAIT0; } else { CP_WAIT1; }
        __syncthreads();
        if (kt + 2 < nk) stage((kt + 2) << 5, s_nxt);
        const uint32_t aB = aBase[s_cur];
        const uint32_t bB = bBase[s_cur];
        #pragma unroll
        for (int kk = 0; kk < 4; kk++) {
            uint32_t av[4][4], bv[8][2];
            #pragma unroll
            for (int mf = 0; mf < 4; mf++)
                ldm_x4(av[mf], aB + aRow[mf] + ((((kk << 1) + qhiA) ^ rowin) << 4));
            #pragma unroll
            for (int p = 0; p < 4; p++) {
                uint32_t t[4];
                ldm_x4(t, bB + bRow[p] + ((((kk << 1) + qhiB) ^ rowin) << 4));
                bv[2 * p][0] = t[0]; bv[2 * p][1] = t[1];
                bv[2 * p + 1][0] = t[2]; bv[2 * p + 1][1] = t[3];
            }
            #pragma unroll
            for (int mf = 0; mf < 4; mf++)
                #pragma unroll
                for (int nf = 0; nf < 8; nf++)
                    mma_tf32(acc[mf][nf], av[mf], bv[nf]);
        }
        s_cur = (s_cur + 1) % 3;
        s_nxt = (s_nxt + 1) % 3;
    }

    // epilogue
    #pragma unroll
    for (int mf = 0; mf < 4; mf++) {
        #pragma unroll
        for (int half = 0; half < 2; half++) {
            int rw = bm + wm * 64 + mf * 16 + gr + half * 8;
            float bvv = (BIAS_MODE == 1) ? bias[rw] : 0.f;
            #pragma unroll
            for (int nf = 0; nf < 8; nf++) {
                int cl = bn + wn * 64 + nf * 8 + t4 * 2;
                float2 o;
                o.x = acc[mf][nf][half * 2 + 0] * alpha + bvv;
                o.y = acc[mf][nf][half * 2 + 1] * alpha + bvv;
                if (BIAS_MODE == 2) { o.x += bias[cl]; o.y += bias[cl + 1]; }
                if (HAS_SKIP) {
                    o.x += skip[(size_t)cl * ldsk + rw];
                    o.y += skip[(size_t)(cl + 1) * ldsk + rw];
                }
                *reinterpret_cast<float2*>(&Cm[(size_t)rw * ldc + cl]) = o;
            }
        }
    }
}

// ---------------------------------------------------------------------------
// FP32 SGEMM (q/skip path — feeds the skip add, must stay fp32-accurate).
// C[m,n] = sum_k A(m,k)*B(n,k) + bias[n].  A,B K-major.
// ---------------------------------------------------------------------------
__global__ __launch_bounds__(256, 2)
void sgemm_q(const float* __restrict__ A, int lda, long long sA,
             const float* __restrict__ Bm, int ldb,
             float* __restrict__ Cm, int ldc, long long sC,
             int K, const float* __restrict__ bias) {
    const int bz = blockIdx.z;
    A  += (size_t)bz * sA;
    Cm += (size_t)bz * sC;

    const int bm = blockIdx.x * 128, bn = blockIdx.y * 128;
    __shared__ float As[2][8][128];
    __shared__ float Bs[2][8][128];
    const int tid = threadIdx.x;
    const int tm  = tid >> 1, tkq = (tid & 1) << 2;

    float acc[8][8];
    #pragma unroll
    for (int i = 0; i < 8; i++)
        #pragma unroll
        for (int j = 0; j < 8; j++) acc[i][j] = 0.f;

    auto ldgA = [&](int k0) -> float4 {
        return *reinterpret_cast<const float4*>(&A[(size_t)(bm + tm) * lda + k0 + tkq]);
    };
    auto ldgB = [&](int k0) -> float4 {
        return *reinterpret_cast<const float4*>(&Bm[(size_t)(bn + tm) * ldb + k0 + tkq]);
    };
    auto stsA = [&](float4 v, int buf) {
        As[buf][tkq + 0][tm] = v.x; As[buf][tkq + 1][tm] = v.y;
        As[buf][tkq + 2][tm] = v.z; As[buf][tkq + 3][tm] = v.w;
    };
    auto stsB = [&](float4 v, int buf) {
        Bs[buf][tkq + 0][tm] = v.x; Bs[buf][tkq + 1][tm] = v.y;
        Bs[buf][tkq + 2][tm] = v.z; Bs[buf][tkq + 3][tm] = v.w;
    };

    float4 pa = ldgA(0), pb = ldgB(0);
    stsA(pa, 0); stsB(pb, 0);
    __syncthreads();

    const int nk = K >> 3;
    const int tx = tid & 15, ty = tid >> 4;
    for (int kt = 0; kt < nk; kt++) {
        const int cur = kt & 1;
        const bool pre = (kt + 1 < nk);
        if (pre) { pa = ldgA((kt + 1) << 3); pb = ldgB((kt + 1) << 3); }
        #pragma unroll
        for (int k = 0; k < 8; k++) {
            float4 a0 = *reinterpret_cast<const float4*>(&As[cur][k][ty << 2]);
            float4 a1 = *reinterpret_cast<const float4*>(&As[cur][k][64 + (ty << 2)]);
            float4 b0 = *reinterpret_cast<const float4*>(&Bs[cur][k][tx << 2]);
            float4 b1 = *reinterpret_cast<const float4*>(&Bs[cur][k][64 + (tx << 2)]);
            float av[8] = {a0.x, a0.y, a0.z, a0.w, a1.x, a1.y, a1.z, a1.w};
            float bv[8] = {b0.x, b0.y, b0.z, b0.w, b1.x, b1.y, b1.z, b1.w};
            #pragma unroll
            for (int i = 0; i < 8; i++)
                #pragma unroll
                for (int j = 0; j < 8; j++)
                    acc[i][j] = fmaf(av[i], bv[j], acc[i][j]);
        }
        if (pre) { stsA(pa, cur ^ 1); stsB(pb, cur ^ 1); }
        __syncthreads();
    }

    #pragma unroll
    for (int i = 0; i < 8; i++) {
        int row = bm + ((i < 4) ? (ty * 4 + i) : (64 + ty * 4 + i - 4));
        #pragma unroll
        for (int jh = 0; jh < 2; jh++) {
            int col = bn + jh * 64 + tx * 4;
            float4 bc = *reinterpret_cast<const float4*>(&bias[col]);
            float4 o;
            o.x = acc[i][jh * 4 + 0] + bc.x;
            o.y = acc[i][jh * 4 + 1] + bc.y;
            o.z = acc[i][jh * 4 + 2] + bc.z;
            o.w = acc[i][jh * 4 + 3] + bc.w;
            *reinterpret_cast<float4*>(&Cm[(size_t)row * ldc + col]) = o;
        }
    }
}

// ---------------------------------------------------------------------------
// Row softmax over 6912 elems; one block per row, register-resident.
// ---------------------------------------------------------------------------
__global__ void softmax_kernel(float* __restrict__ sc) {
    __shared__ float red[8];
    __shared__ float bmax, bsum;
    const int tid = threadIdx.x;
    float* row = sc + (size_t)blockIdx.x * N3;

    float vals[27];
    float mx = -1e30f;
    #pragma unroll
    for (int i = 0; i < 27; i++) {
        vals[i] = row[i * 256 + tid];
        mx = fmaxf(mx, vals[i]);
    }
    #pragma unroll
    for (int o = 16; o; o >>= 1) mx = fmaxf(mx, __shfl_xor_sync(0xffffffffu, mx, o));
    if ((tid & 31) == 0) red[tid >> 5] = mx;
    __syncthreads();
    if (tid < 32) {
        float t = (tid < 8) ? red[tid] : -1e30f;
        #pragma unroll
        for (int o = 4; o; o >>= 1) t = fmaxf(t, __shfl_xor_sync(0xffffffffu, t, o));
        if (tid == 0) bmax = t;
    }
    __syncthreads();
    mx = bmax;

    float s = 0.f;
    #pragma unroll
    for (int i = 0; i < 27; i++) { vals[i] = __expf(vals[i] - mx); s += vals[i]; }
    #pragma unroll
    for (int o = 16; o; o >>= 1) s += __shfl_xor_sync(0xffffffffu, s, o);
    if ((tid & 31) == 0) red[tid >> 5] = s;
    __syncthreads();
    if (tid < 32) {
        float t = (tid < 8) ? red[tid] : 0.f;
        #pragma unroll
        for (int o = 4; o; o >>= 1) t += __shfl_xor_sync(0xffffffffu, t, o);
        if (tid == 0) bsum = t;
    }
    __syncthreads();
    float inv = 1.f / bsum;
    #pragma unroll
    for (int i = 0; i < 27; i++) row[i * 256 + tid] = vals[i] * inv;
}

// ---------------------------------------------------------------------------
// Launch
// ---------------------------------------------------------------------------
extern "C" void kernel_launch(void* const* d_in, const int* in_sizes, int n_in,
                              void* d_out, int out_size) {
    const float* x   = (const float*)d_in[0];
    const float* nsc = (const float*)d_in[1];
    const float* nbi = (const float*)d_in[2];
    const float* q_w = (const float*)d_in[3];
    const float* q_b = (const float*)d_in[4];
    const float* k_w = (const float*)d_in[5];
    const float* k_b = (const float*)d_in[6];
    const float* v_w = (const float*)d_in[7];
    const float* v_b = (const float*)d_in[8];
    const float* p_w = (const float*)d_in[9];
    const float* p_b = (const float*)d_in[10];
    float* out = (float*)d_out;

    float *hnt, *qt, *kt, *v, *sc, *ot;
    cudaGetSymbolAddress((void**)&hnt, g_hnt);
    cudaGetSymbolAddress((void**)&qt,  g_qt);
    cudaGetSymbolAddress((void**)&kt,  g_kt);
    cudaGetSymbolAddress((void**)&v,   g_v);
    cudaGetSymbolAddress((void**)&sc,  g_sc);
    cudaGetSymbolAddress((void**)&ot,  g_ot);

    cudaFuncSetAttribute(mma_gemm<0, false>, cudaFuncAttributeMaxDynamicSharedMemorySize, GEMM_SMEM);
    cudaFuncSetAttribute(mma_gemm<1, false>, cudaFuncAttributeMaxDynamicSharedMemorySize, GEMM_SMEM);
    cudaFuncSetAttribute(mma_gemm<2, false>, cudaFuncAttributeMaxDynamicSharedMemorySize, GEMM_SMEM);
    cudaFuncSetAttribute(mma_gemm<1, true>,  cudaFuncAttributeMaxDynamicSharedMemorySize, GEMM_SMEM);

    const long long sHnt = (long long)N3 * C;
    const long long sQt  = (long long)HW * C;
    const long long sKt  = (long long)N3 * C;
    const long long sV   = (long long)C * N3;
    const long long sSc  = (long long)HW * N3;
    const long long sOt  = (long long)HW * C;

    // GroupNorm (+ transpose into hnt)
    zero_stats_kernel<<<1, 32>>>();
    gn_stats_kernel<<<dim3(B * G, 16), 256>>>(x);
    gn_apply_t_kernel<<<dim3(HW / 32, C / 32, B * T), dim3(32, 8)>>>(x, nsc, nbi);

    // qt[p][o] = hnt[t=1][p][:] . q_w[o][:] + q_b[o]   (fp32 — skip path)
    sgemm_q<<<dim3(HW / 128, C / 128, B), 256>>>(
        hnt + (size_t)HW * C, C, sHnt, q_w, C, qt, C, sQt, C, q_b);

    // kt[m][o] = hnt[m][:] . k_w[o][:] + k_b[o]
    mma_gemm<2, false><<<dim3(N3 / 128, C / 256, B), 256, GEMM_SMEM>>>(
        hnt, C, sHnt, k_w, C, 0, kt, C, sKt, C, 1.f, k_b, nullptr, 0, 0);

    // v[c][m] = v_w[c][:] . hnt[m][:] + v_b[c]
    mma_gemm<1, false><<<dim3(C / 128, N3 / 256, B), 256, GEMM_SMEM>>>(
        v_w, C, 0, hnt, C, sHnt, v, N3, sV, C, 1.f, v_b, nullptr, 0, 0);

    // scores[p][m] = (qt[p][:] . kt[m][:]) * C^-0.5
    mma_gemm<0, false><<<dim3(HW / 128, N3 / 256, B), 256, GEMM_SMEM>>>(
        qt, C, sQt, kt, C, sKt, sc, N3, sSc, C, 0.044194173824159216f,
        nullptr, nullptr, 0, 0);

    softmax_kernel<<<B * HW, 256>>>(sc);

    // ot[p][c] = attn[p][:] . v[c][:]
    mma_gemm<0, false><<<dim3(HW / 128, C / 256, B), 256, GEMM_SMEM>>>(
        sc, N3, sSc, v, N3, sV, ot, C, sOt, N3, 1.f, nullptr, nullptr, 0, 0);

    // out[o][p] = p_w[o][:] . ot[p][:] + p_b[o] + qt[p][o]
    mma_gemm<1, true><<<dim3(C / 128, HW / 256, B), 256, GEMM_SMEM>>>(
        p_w, C, 0, ot, C, sOt, out, HW, (long long)C * HW, C, 1.f, p_b,
        qt, C, sQt);
}

// round 8
// speedup vs baseline: 1.9564x; 1.9564x over previous
#include <cuda_runtime.h>
#include <cuda_bf16.h>
#include <cstdint>

constexpr int B  = 4;
constexpr int C  = 512;
constexpr int T  = 3;
constexpr int HW = 2304;   // 48*48
constexpr int N3 = 6912;   // 3*HW
constexpr int G  = 4;
constexpr int CG = C / G;  // 128
constexpr float EPS = 1e-6f;

typedef __nv_bfloat16  bf16;
typedef __nv_bfloat162 bf162;

// Scratch
__device__ bf16  gb_hnt[(size_t)B * N3 * C];   // normalized, transposed, bf16
__device__ float g_hnt1[(size_t)B * HW * C];   // t=1 slice, fp32 (q path)
__device__ float g_qt  [(size_t)B * HW * C];   // q fp32 (skip)
__device__ bf16  gb_qt [(size_t)B * HW * C];   // q bf16 (scores operand)
__device__ bf16  gb_kt [(size_t)B * N3 * C];   // k [m][c]
__device__ bf16  gb_v  [(size_t)B * C * N3];   // v [c][m]
__device__ bf16  gb_sc [(size_t)B * HW * N3];  // scores / attn [p][m]
__device__ bf16  gb_ot [(size_t)B * HW * C];   // attn out [p][c]
__device__ bf16  gb_kw[C * C], gb_vw[C * C], gb_pw[C * C];
__device__ float g_stats[2 * B * G];

__device__ __forceinline__ uint32_t smem_u32(const void* p) {
    return (uint32_t)__cvta_generic_to_shared(p);
}
#define CP_ASYNC16(sm, gm) \
    asm volatile("cp.async.ca.shared.global [%0], [%1], 16;" :: "r"(sm), "l"(gm))
#define CP_COMMIT asm volatile("cp.async.commit_group;")
#define CP_WAIT1  asm volatile("cp.async.wait_group 1;")
#define CP_WAIT0  asm volatile("cp.async.wait_group 0;")

__device__ __forceinline__ void ldm_x4(uint32_t* r, uint32_t addr) {
    asm volatile("ldmatrix.sync.aligned.m8n8.x4.shared.b16 {%0,%1,%2,%3}, [%4];"
        : "=r"(r[0]), "=r"(r[1]), "=r"(r[2]), "=r"(r[3]) : "r"(addr));
}
__device__ __forceinline__ void mma_bf16(float* c, const uint32_t* a, const uint32_t* b) {
    asm volatile("mma.sync.aligned.m16n8k16.row.col.f32.bf16.bf16.f32 "
        "{%0,%1,%2,%3}, {%4,%5,%6,%7}, {%8,%9}, {%0,%1,%2,%3};"
        : "+f"(c[0]), "+f"(c[1]), "+f"(c[2]), "+f"(c[3])
        : "r"(a[0]), "r"(a[1]), "r"(a[2]), "r"(a[3]), "r"(b[0]), "r"(b[1]));
}

// ---------------------------------------------------------------------------
// GroupNorm
// ---------------------------------------------------------------------------
__global__ void zero_stats_kernel() {
    if (threadIdx.x < 2 * B * G) g_stats[threadIdx.x] = 0.f;
}

__global__ void gn_stats_kernel(const float* __restrict__ x) {
    const int bg = blockIdx.x;
    const int b = bg >> 2, g = bg & 3;
    const int TOT4 = CG * T * HW / 4;
    const int PER  = TOT4 / 16;
    const int start = blockIdx.y * PER;

    float s = 0.f, ss = 0.f;
    for (int i = start + threadIdx.x; i < start + PER; i += blockDim.x) {
        int cl = i / (T * HW / 4);
        int r  = i - cl * (T * HW / 4);
        int t  = r / (HW / 4);
        int p4 = r - t * (HW / 4);
        float4 v = reinterpret_cast<const float4*>(x)[
            ((size_t)(t * B + b) * C + g * CG + cl) * (HW / 4) + p4];
        s  += v.x + v.y + v.z + v.w;
        ss += v.x * v.x + v.y * v.y + v.z * v.z + v.w * v.w;
    }
    __shared__ float rs[8], rss[8];
    #pragma unroll
    for (int o = 16; o; o >>= 1) {
        s  += __shfl_xor_sync(0xffffffffu, s, o);
        ss += __shfl_xor_sync(0xffffffffu, ss, o);
    }
    if ((threadIdx.x & 31) == 0) { rs[threadIdx.x >> 5] = s; rss[threadIdx.x >> 5] = ss; }
    __syncthreads();
    if (threadIdx.x == 0) {
        float a = 0.f, c = 0.f;
        #pragma unroll
        for (int i = 0; i < 8; i++) { a += rs[i]; c += rss[i]; }
        atomicAdd(&g_stats[2 * bg],     a);
        atomicAdd(&g_stats[2 * bg + 1], c);
    }
}

// normalize + affine + transpose -> gb_hnt (bf16); t=1 slice also fp32
__global__ void gn_apply_t_kernel(const float* __restrict__ x,
                                  const float* __restrict__ scale,
                                  const float* __restrict__ bias) {
    __shared__ float tile[32][33];
    const int bt = blockIdx.z;
    const int b = bt / T, t = bt - b * T;
    const int p0 = blockIdx.x << 5, c0 = blockIdx.y << 5;
    const int tx = threadIdx.x, ty = threadIdx.y;  // 32 x 8
    const float nrm = 1.f / (float)(CG * T * HW);

    #pragma unroll
    for (int kk = 0; kk < 4; kk++) {
        int c = c0 + ty + kk * 8;
        int g = c >> 7;
        float sum = g_stats[2 * (b * G + g)];
        float sq  = g_stats[2 * (b * G + g) + 1];
        float mean = sum * nrm;
        float var  = sq * nrm - mean * mean;
        float rstd = rsqrtf(var + EPS);
        float a = rstd * scale[c];
        float d = bias[c] - mean * a;
        float v = x[((size_t)(t * B + b) * C + c) * HW + p0 + tx];
        tile[ty + kk * 8][tx] = v * a + d;
    }
    __syncthreads();
    #pragma unroll
    for (int kk = 0; kk < 4; kk++) {
        int p = p0 + ty + kk * 8;
        float v = tile[tx][ty + kk * 8];
        gb_hnt[(size_t)b * N3 * C + (size_t)(t * HW + p) * C + c0 + tx] = __float2bfloat16(v);
        if (t == 1)
            g_hnt1[(size_t)b * HW * C + (size_t)p * C + c0 + tx] = v;
    }
}

// Convert the three weight matrices to bf16
__global__ void wconv_kernel(const float* __restrict__ kw,
                             const float* __restrict__ vw,
                             const float* __restrict__ pw) {
    int i = blockIdx.x * blockDim.x + threadIdx.x;
    if (i < C * C) {
        gb_kw[i] = __float2bfloat16(kw[i]);
        gb_vw[i] = __float2bfloat16(vw[i]);
        gb_pw[i] = __float2bfloat16(pw[i]);
    }
}

// ---------------------------------------------------------------------------
// BF16 mma.sync GEMM: 128x128 tile, BK=64, 8 warps (2x4), warp 64x32,
// m16n8k16, 2-stage cp.async, quad-XOR swizzle (tile = 128 rows x 128B).
// C[m,n] = alpha * sum_k A[m,k]*Bm[n,k] (+bias) (+skip^T). K-major operands.
// BIAS_MODE: 0 none, 1 bias[row m], 2 bias[col n].
// OUT_F32: write fp32 to Cf (proj+skip) else bf16 to Cb.
// ---------------------------------------------------------------------------
constexpr int GEMM_SMEM = 2 * 2 * 128 * 128;   // 65536 bytes

template <int BIAS_MODE, bool HAS_SKIP, bool OUT_F32>
__global__ __launch_bounds__(256, 2)
void mma_gemm(const bf16* __restrict__ A, int lda, long long sA,
              const bf16* __restrict__ Bm, int ldb, long long sB,
              float* __restrict__ Cf, bf16* __restrict__ Cb, int ldc, long long sC,
              int K, float alpha, const float* __restrict__ bias,
              const float* __restrict__ skip, int ldsk, long long sSk) {
    extern __shared__ __align__(16) char dsm[];

    const int bz = blockIdx.z;
    A  += (size_t)bz * sA;
    Bm += (size_t)bz * sB;
    if (OUT_F32) Cf += (size_t)bz * sC; else Cb += (size_t)bz * sC;
    if (HAS_SKIP) skip += (size_t)bz * sSk;

    const int bm = blockIdx.x * 128, bn = blockIdx.y * 128;
    const int tid = threadIdx.x, wid = tid >> 5, lane = tid & 31;
    const int wm = wid & 1, wn = wid >> 1;      // warp grid 2 (M) x 4 (N)
    const int gr = lane >> 2, t4 = lane & 3;
    const int grp = lane >> 3, rowin = lane & 7;
    const int qhiA = grp >> 1;                  // A: k-chunk parity per lane group
    const int qhiB = grp & 1;                   // B: k-chunk parity per lane group

    // staging: thread -> row r = tid>>1, 16B chunks q0..q0+3 of that row
    const int r  = tid >> 1;
    const int q0 = (tid & 1) * 4;
    const bf16* Arow = A  + (size_t)(bm + r) * lda;
    const bf16* Brow = Bm + (size_t)(bn + r) * ldb;
    uint32_t off[4];
    #pragma unroll
    for (int j = 0; j < 4; j++)
        off[j] = r * 128 + (((q0 + j) ^ (r & 7)) << 4);   // bytes within 16KB tile
    const uint32_t smBase = smem_u32(dsm);
    // layout: [buf0 A | buf0 B | buf1 A | buf1 B], 16KB each
    auto stage = [&](int k0, int buf) {
        uint32_t ab = smBase + buf * 32768;
        uint32_t bb = ab + 16384;
        #pragma unroll
        for (int j = 0; j < 4; j++) {
            CP_ASYNC16(ab + off[j], Arow + k0 + (q0 + j) * 8);
            CP_ASYNC16(bb + off[j], Brow + k0 + (q0 + j) * 8);
        }
        CP_COMMIT;
    };

    // fragment row byte-offsets
    uint32_t aRow[4], bRow[2];
    #pragma unroll
    for (int mf = 0; mf < 4; mf++)
        aRow[mf] = (uint32_t)(wm * 64 + mf * 16 + (grp & 1) * 8 + rowin) * 128;
    #pragma unroll
    for (int p = 0; p < 2; p++)
        bRow[p] = (uint32_t)(wn * 32 + p * 16 + (grp >> 1) * 8 + rowin) * 128;

    float acc[4][4][4];
    #pragma unroll
    for (int i = 0; i < 4; i++)
        #pragma unroll
        for (int j = 0; j < 4; j++)
            #pragma unroll
            for (int q = 0; q < 4; q++) acc[i][j][q] = 0.f;

    const int nk = K >> 6;                      // BK = 64 bf16
    stage(0, 0);
    for (int kt = 0; kt < nk; kt++) {
        if (kt + 1 < nk) { stage((kt + 1) << 6, (kt + 1) & 1); CP_WAIT1; }
        else             { CP_WAIT0; }
        __syncthreads();
        const uint32_t aB = smBase + (kt & 1) * 32768;
        const uint32_t bB = aB + 16384;
        #pragma unroll
        for (int kk = 0; kk < 4; kk++) {        // 4 x K16 per tile
            uint32_t av[4][4], bv[4][2];
            #pragma unroll
            for (int mf = 0; mf < 4; mf++)
                ldm_x4(av[mf], aB + aRow[mf] + ((((kk << 1) + qhiA) ^ rowin) << 4));
            #pragma unroll
            for (int p = 0; p < 2; p++) {
                uint32_t t[4];
                ldm_x4(t, bB + bRow[p] + ((((kk << 1) + qhiB) ^ rowin) << 4));
                bv[2 * p][0] = t[0]; bv[2 * p][1] = t[1];
                bv[2 * p + 1][0] = t[2]; bv[2 * p + 1][1] = t[3];
            }
            #pragma unroll
            for (int mf = 0; mf < 4; mf++)
                #pragma unroll
                for (int nf = 0; nf < 4; nf++)
                    mma_bf16(acc[mf][nf], av[mf], bv[nf]);
        }
        __syncthreads();
    }

    // epilogue
    #pragma unroll
    for (int mf = 0; mf < 4; mf++) {
        #pragma unroll
        for (int half = 0; half < 2; half++) {
            int rw = bm + wm * 64 + mf * 16 + gr + half * 8;
            float bvv = (BIAS_MODE == 1) ? bias[rw] : 0.f;
            #pragma unroll
            for (int nf = 0; nf < 4; nf++) {
                int cl = bn + wn * 32 + nf * 8 + t4 * 2;
                float ox = acc[mf][nf][half * 2 + 0] * alpha + bvv;
                float oy = acc[mf][nf][half * 2 + 1] * alpha + bvv;
                if (BIAS_MODE == 2) { ox += bias[cl]; oy += bias[cl + 1]; }
                if (HAS_SKIP) {
                    ox += skip[(size_t)cl * ldsk + rw];
                    oy += skip[(size_t)(cl + 1) * ldsk + rw];
                }
                if (OUT_F32) {
                    *reinterpret_cast<float2*>(&Cf[(size_t)rw * ldc + cl]) =
                        make_float2(ox, oy);
                } else {
                    *reinterpret_cast<bf162*>(&Cb[(size_t)rw * ldc + cl]) =
                        __floats2bfloat162_rn(ox, oy);
                }
            }
        }
    }
}

// ---------------------------------------------------------------------------
// FP32 SGEMM (q/skip path). C[m,n] = sum_k A(m,k)*B(n,k) + bias[n].
// Writes fp32 (skip) AND bf16 (scores operand).
// ---------------------------------------------------------------------------
__global__ __launch_bounds__(256, 2)
void sgemm_q(const float* __restrict__ A, int lda, long long sA,
             const float* __restrict__ Bm, int ldb,
             float* __restrict__ Cm, bf16* __restrict__ Cb, int ldc, long long sC,
             int K, const float* __restrict__ bias) {
    const int bz = blockIdx.z;
    A  += (size_t)bz * sA;
    Cm += (size_t)bz * sC;
    Cb += (size_t)bz * sC;

    const int bm = blockIdx.x * 128, bn = blockIdx.y * 128;
    __shared__ float As[2][8][128];
    __shared__ float Bs[2][8][128];
    const int tid = threadIdx.x;
    const int tm  = tid >> 1, tkq = (tid & 1) << 2;

    float acc[8][8];
    #pragma unroll
    for (int i = 0; i < 8; i++)
        #pragma unroll
        for (int j = 0; j < 8; j++) acc[i][j] = 0.f;

    auto ldgA = [&](int k0) -> float4 {
        return *reinterpret_cast<const float4*>(&A[(size_t)(bm + tm) * lda + k0 + tkq]);
    };
    auto ldgB = [&](int k0) -> float4 {
        return *reinterpret_cast<const float4*>(&Bm[(size_t)(bn + tm) * ldb + k0 + tkq]);
    };
    auto stsA = [&](float4 v, int buf) {
        As[buf][tkq + 0][tm] = v.x; As[buf][tkq + 1][tm] = v.y;
        As[buf][tkq + 2][tm] = v.z; As[buf][tkq + 3][tm] = v.w;
    };
    auto stsB = [&](float4 v, int buf) {
        Bs[buf][tkq + 0][tm] = v.x; Bs[buf][tkq + 1][tm] = v.y;
        Bs[buf][tkq + 2][tm] = v.z; Bs[buf][tkq + 3][tm] = v.w;
    };

    float4 pa = ldgA(0), pb = ldgB(0);
    stsA(pa, 0); stsB(pb, 0);
    __syncthreads();

    const int nk = K >> 3;
    const int tx = tid & 15, ty = tid >> 4;
    for (int kt = 0; kt < nk; kt++) {
        const int cur = kt & 1;
        const bool pre = (kt + 1 < nk);
        if (pre) { pa = ldgA((kt + 1) << 3); pb = ldgB((kt + 1) << 3); }
        #pragma unroll
        for (int k = 0; k < 8; k++) {
            float4 a0 = *reinterpret_cast<const float4*>(&As[cur][k][ty << 2]);
            float4 a1 = *reinterpret_cast<const float4*>(&As[cur][k][64 + (ty << 2)]);
            float4 b0 = *reinterpret_cast<const float4*>(&Bs[cur][k][tx << 2]);
            float4 b1 = *reinterpret_cast<const float4*>(&Bs[cur][k][64 + (tx << 2)]);
            float av[8] = {a0.x, a0.y, a0.z, a0.w, a1.x, a1.y, a1.z, a1.w};
            float bv[8] = {b0.x, b0.y, b0.z, b0.w, b1.x, b1.y, b1.z, b1.w};
            #pragma unroll
            for (int i = 0; i < 8; i++)
                #pragma unroll
                for (int j = 0; j < 8; j++)
                    acc[i][j] = fmaf(av[i], bv[j], acc[i][j]);
        }
        if (pre) { stsA(pa, cur ^ 1); stsB(pb, cur ^ 1); }
        __syncthreads();
    }

    #pragma unroll
    for (int i = 0; i < 8; i++) {
        int row = bm + ((i < 4) ? (ty * 4 + i) : (64 + ty * 4 + i - 4));
        #pragma unroll
        for (int jh = 0; jh < 2; jh++) {
            int col = bn + jh * 64 + tx * 4;
            float4 bc = *reinterpret_cast<const float4*>(&bias[col]);
            float4 o;
            o.x = acc[i][jh * 4 + 0] + bc.x;
            o.y = acc[i][jh * 4 + 1] + bc.y;
            o.z = acc[i][jh * 4 + 2] + bc.z;
            o.w = acc[i][jh * 4 + 3] + bc.w;
            *reinterpret_cast<float4*>(&Cm[(size_t)row * ldc + col]) = o;
            bf162* cb = reinterpret_cast<bf162*>(&Cb[(size_t)row * ldc + col]);
            cb[0] = __floats2bfloat162_rn(o.x, o.y);
            cb[1] = __floats2bfloat162_rn(o.z, o.w);
        }
    }
}

// ---------------------------------------------------------------------------
// Row softmax over 6912 bf16 elems; 128 threads/row, fp32 math.
// ---------------------------------------------------------------------------
__global__ void softmax_kernel(bf16* __restrict__ sc) {
    __shared__ float red[4];
    __shared__ float bmax, bsum;
    const int tid = threadIdx.x;
    bf162* row = reinterpret_cast<bf162*>(sc + (size_t)blockIdx.x * N3);

    float2 vals[27];
    float mx = -1e30f;
    #pragma unroll
    for (int i = 0; i < 27; i++) {
        vals[i] = __bfloat1622float2(row[i * 128 + tid]);
        mx = fmaxf(mx, fmaxf(vals[i].x, vals[i].y));
    }
    #pragma unroll
    for (int o = 16; o; o >>= 1) mx = fmaxf(mx, __shfl_xor_sync(0xffffffffu, mx, o));
    if ((tid & 31) == 0) red[tid >> 5] = mx;
    __syncthreads();
    if (tid < 32) {
        float t = (tid < 4) ? red[tid] : -1e30f;
        #pragma unroll
        for (int o = 2; o; o >>= 1) t = fmaxf(t, __shfl_xor_sync(0xffffffffu, t, o));
        if (tid == 0) bmax = t;
    }
    __syncthreads();
    mx = bmax;

    float s = 0.f;
    #pragma unroll
    for (int i = 0; i < 27; i++) {
        vals[i].x = __expf(vals[i].x - mx);
        vals[i].y = __expf(vals[i].y - mx);
        s += vals[i].x + vals[i].y;
    }
    #pragma unroll
    for (int o = 16; o; o >>= 1) s += __shfl_xor_sync(0xffffffffu, s, o);
    if ((tid & 31) == 0) red[tid >> 5] = s;
    __syncthreads();
    if (tid < 32) {
        float t = (tid < 4) ? red[tid] : 0.f;
        #pragma unroll
        for (int o = 2; o; o >>= 1) t += __shfl_xor_sync(0xffffffffu, t, o);
        if (tid == 0) bsum = t;
    }
    __syncthreads();
    float inv = 1.f / bsum;
    #pragma unroll
    for (int i = 0; i < 27; i++)
        row[i * 128 + tid] = __floats2bfloat162_rn(vals[i].x * inv, vals[i].y * inv);
}

// ---------------------------------------------------------------------------
// Launch
// ---------------------------------------------------------------------------
extern "C" void kernel_launch(void* const* d_in, const int* in_sizes, int n_in,
                              void* d_out, int out_size) {
    const float* x   = (const float*)d_in[0];
    const float* nsc = (const float*)d_in[1];
    const float* nbi = (const float*)d_in[2];
    const float* q_w = (const float*)d_in[3];
    const float* q_b = (const float*)d_in[4];
    const float* k_w = (const float*)d_in[5];
    const float* k_b = (const float*)d_in[6];
    const float* v_w = (const float*)d_in[7];
    const float* v_b = (const float*)d_in[8];
    const float* p_w = (const float*)d_in[9];
    const float* p_b = (const float*)d_in[10];
    float* out = (float*)d_out;

    bf16 *hntb, *qtb, *ktb, *vb, *scb, *otb, *kwb, *vwb, *pwb;
    float *hnt1, *qt;
    cudaGetSymbolAddress((void**)&hntb, gb_hnt);
    cudaGetSymbolAddress((void**)&hnt1, g_hnt1);
    cudaGetSymbolAddress((void**)&qt,   g_qt);
    cudaGetSymbolAddress((void**)&qtb,  gb_qt);
    cudaGetSymbolAddress((void**)&ktb,  gb_kt);
    cudaGetSymbolAddress((void**)&vb,   gb_v);
    cudaGetSymbolAddress((void**)&scb,  gb_sc);
    cudaGetSymbolAddress((void**)&otb,  gb_ot);
    cudaGetSymbolAddress((void**)&kwb,  gb_kw);
    cudaGetSymbolAddress((void**)&vwb,  gb_vw);
    cudaGetSymbolAddress((void**)&pwb,  gb_pw);

    cudaFuncSetAttribute(mma_gemm<0, false, false>, cudaFuncAttributeMaxDynamicSharedMemorySize, GEMM_SMEM);
    cudaFuncSetAttribute(mma_gemm<1, false, false>, cudaFuncAttributeMaxDynamicSharedMemorySize, GEMM_SMEM);
    cudaFuncSetAttribute(mma_gemm<2, false, false>, cudaFuncAttributeMaxDynamicSharedMemorySize, GEMM_SMEM);
    cudaFuncSetAttribute(mma_gemm<1, true,  true >, cudaFuncAttributeMaxDynamicSharedMemorySize, GEMM_SMEM);

    const long long sHnt = (long long)N3 * C;
    const long long sH1  = (long long)HW * C;
    const long long sQt  = (long long)HW * C;
    const long long sKt  = (long long)N3 * C;
    const long long sV   = (long long)C * N3;
    const long long sSc  = (long long)HW * N3;
    const long long sOt  = (long long)HW * C;

    // GroupNorm (+ transpose) and weight conversion
    zero_stats_kernel<<<1, 32>>>();
    gn_stats_kernel<<<dim3(B * G, 16), 256>>>(x);
    gn_apply_t_kernel<<<dim3(HW / 32, C / 32, B * T), dim3(32, 8)>>>(x, nsc, nbi);
    wconv_kernel<<<(C * C + 255) / 256, 256>>>(k_w, v_w, p_w);

    // qt[p][o] = hnt1[p][:] . q_w[o][:] + q_b[o]   (fp32 skip + bf16 copy)
    sgemm_q<<<dim3(HW / 128, C / 128, B), 256>>>(
        hnt1, C, sH1, q_w, C, qt, qtb, C, sQt, C, q_b);

    // kt[m][o] = hnt[m][:] . k_w[o][:] + k_b[o]
    mma_gemm<2, false, false><<<dim3(N3 / 128, C / 128, B), 256, GEMM_SMEM>>>(
        hntb, C, sHnt, kwb, C, 0, nullptr, ktb, C, sKt, C, 1.f, k_b, nullptr, 0, 0);

    // v[c][m] = v_w[c][:] . hnt[m][:] + v_b[c]
    mma_gemm<1, false, false><<<dim3(C / 128, N3 / 128, B), 256, GEMM_SMEM>>>(
        vwb, C, 0, hntb, C, sHnt, nullptr, vb, N3, sV, C, 1.f, v_b, nullptr, 0, 0);

    // scores[p][m] = (qt[p][:] . kt[m][:]) * C^-0.5
    mma_gemm<0, false, false><<<dim3(HW / 128, N3 / 128, B), 256, GEMM_SMEM>>>(
        qtb, C, sQt, ktb, C, sKt, nullptr, scb, N3, sSc, C,
        0.044194173824159216f, nullptr, nullptr, 0, 0);

    softmax_kernel<<<B * HW, 128>>>(scb);

    // ot[p][c] = attn[p][:] . v[c][:]
    mma_gemm<0, false, false><<<dim3(HW / 128, C / 128, B), 256, GEMM_SMEM>>>(
        scb, N3, sSc, vb, N3, sV, nullptr, otb, C, sOt, N3, 1.f,
        nullptr, nullptr, 0, 0);

    // out[o][p] = p_w[o][:] . ot[p][:] + p_b[o] + qt[p][o]   (fp32 out)
    mma_gemm<1, true, true><<<dim3(C / 128, HW / 128, B), 256, GEMM_SMEM>>>(
        pwb, C, 0, otb, C, sOt, out, nullptr, HW, (long long)C * HW, C, 1.f, p_b,
        qt, C, sQt);
}